// round 1
// baseline (speedup 1.0000x reference)
#include <cuda_runtime.h>
#include <cstdint>

// ---------------------------------------------------------------------------
// SplineCouplingLayer fused kernel (round 1: fp32 + packed f32x2 FMA)
//
//  x[B,64] -> split 32/32
//  h1 = relu(xm @ W1 + b1)        [B,512]
//  h2 = relu(h1 @ W2 + b2)        [B,512]
//  raw = h2 @ W3 + b3             [B,736] = [B,32,23]
//  (y_t, ld) = rq_spline(x_t, raw)
//  out = [ y[B,64] , sum_ld[B] ]   (flattened tuple order)
// ---------------------------------------------------------------------------

#define B_ROWS  131072
#define DIM     64
#define D_IN    32
#define D_OUT   32
#define HIDDEN  512
#define OUTD    736          // 32 * 23
#define TAILB   3.0f

#define TM      32           // rows per block
#define THREADS 256
#define HSTR    34           // padded stride (even -> 8B-aligned row pairs)
#define KC3     16           // k-chunk for stage 3 W3 staging

// smem layout (float offsets)
#define OFF_H1  0
#define OFF_H2  (OFF_H1 + HIDDEN * HSTR)             // 17408
#define OFF_W3  (OFF_H2 + HIDDEN * HSTR)             // 34816
#define OFF_XM  (OFF_W3 + KC3 * OUTD)                // 46592
#define OFF_XT  (OFF_XM + D_IN * HSTR)               // 47680
#define SMEM_FLOATS (OFF_XT + D_OUT * HSTR)          // 48768 -> 195072 bytes

typedef unsigned long long ull;

__device__ __forceinline__ ull pk(float lo, float hi) {
    ull r; asm("mov.b64 %0, {%1, %2};" : "=l"(r) : "f"(lo), "f"(hi)); return r;
}
__device__ __forceinline__ void unpk(ull v, float &lo, float &hi) {
    asm("mov.b64 {%0, %1}, %2;" : "=f"(lo), "=f"(hi) : "l"(v));
}
// packed 2-wide fp32 FMA (Blackwell sm_100+): d = a*b + d elementwise on halves
__device__ __forceinline__ void fma2(ull &d, ull a, ull b) {
    asm("fma.rn.f32x2 %0, %1, %2, %0;" : "+l"(d) : "l"(a), "l"(b));
}

// ---------------------------------------------------------------------------
// One MLP layer: out[32, 512] = relu(aT^T @ W + bias), a/out stored transposed
// in smem as [col][row] with stride HSTR. Per-thread 8 rows x 8 cols, rows
// packed in f32x2 pairs. W read from global (L1/L2 resident).
// ---------------------------------------------------------------------------
template<int K>
__device__ __forceinline__ void mlp_layer(const float* __restrict__ aT,
                                          const float* __restrict__ W,
                                          const float* __restrict__ bias,
                                          float* __restrict__ outT, int tid)
{
    const int cg = tid & 63;      // 64 col groups
    const int rg = tid >> 6;      // 4  row groups
    const int c0 = cg * 8;
    const int r0 = rg * 8;

    ull acc[8][4];                // [col][rowpair]
#pragma unroll
    for (int j = 0; j < 8; ++j) {
        float bv = bias[c0 + j];
        ull bb = pk(bv, bv);
#pragma unroll
        for (int p = 0; p < 4; ++p) acc[j][p] = bb;
    }

#pragma unroll 4
    for (int k = 0; k < K; ++k) {
        ull a2[4];
#pragma unroll
        for (int p = 0; p < 4; ++p)
            a2[p] = *reinterpret_cast<const ull*>(aT + k * HSTR + r0 + 2 * p);
        float4 bA = *reinterpret_cast<const float4*>(W + k * HIDDEN + c0);
        float4 bB = *reinterpret_cast<const float4*>(W + k * HIDDEN + c0 + 4);
        ull bb[8];
        bb[0] = pk(bA.x, bA.x); bb[1] = pk(bA.y, bA.y);
        bb[2] = pk(bA.z, bA.z); bb[3] = pk(bA.w, bA.w);
        bb[4] = pk(bB.x, bB.x); bb[5] = pk(bB.y, bB.y);
        bb[6] = pk(bB.z, bB.z); bb[7] = pk(bB.w, bB.w);
#pragma unroll
        for (int j = 0; j < 8; ++j)
#pragma unroll
            for (int p = 0; p < 4; ++p)
                fma2(acc[j][p], a2[p], bb[j]);
    }

#pragma unroll
    for (int j = 0; j < 8; ++j)
#pragma unroll
        for (int p = 0; p < 4; ++p) {
            float lo, hi; unpk(acc[j][p], lo, hi);
            lo = fmaxf(lo, 0.f); hi = fmaxf(hi, 0.f);
            float* o = outT + (c0 + j) * HSTR + r0 + 2 * p;
            o[0] = lo; o[1] = hi;
        }
}

// ---------------------------------------------------------------------------
// Rational-quadratic spline (register-resident, SEL-chain gathers)
// ---------------------------------------------------------------------------
__device__ __forceinline__ float softplusf(float z) {
    return (z > 20.f) ? z : log1pf(expf(z));
}

__device__ __forceinline__ void spline_eval(const float raw[23], float xv,
                                            float &y_out, float &ld_out)
{
    float w[8], h[8];
    float mw = raw[0], mh = raw[8];
#pragma unroll
    for (int i = 1; i < 8; ++i) { mw = fmaxf(mw, raw[i]); mh = fmaxf(mh, raw[8 + i]); }
    float sw = 0.f, sh = 0.f;
#pragma unroll
    for (int i = 0; i < 8; ++i) {
        w[i] = expf(raw[i] - mw);     sw += w[i];
        h[i] = expf(raw[8 + i] - mh); sh += h[i];
    }
    float iw = 6.f / sw, ih = 6.f / sh;   // softmax * 2*tail_bound
#pragma unroll
    for (int i = 0; i < 8; ++i) { w[i] *= iw; h[i] *= ih; }

    float der[9];
    der[0] = 1.f; der[8] = 1.f;
#pragma unroll
    for (int i = 0; i < 7; ++i) der[i + 1] = softplusf(raw[16 + i]);

    float cw[9], ch[9];
    cw[0] = -TAILB; ch[0] = -TAILB;
#pragma unroll
    for (int i = 0; i < 8; ++i) { cw[i + 1] = cw[i] + w[i]; ch[i + 1] = ch[i] + h[i]; }

    bool inside = (xv >= -TAILB) && (xv <= TAILB);
    float xc = fminf(fmaxf(xv, -TAILB + 1e-6f), TAILB - 1e-6f);

    int idx = 0;
#pragma unroll
    for (int i = 1; i <= 8; ++i) idx += (cw[i] < xc) ? 1 : 0;
    idx = min(idx, 7);

    float wk = w[0], hk = h[0], dk = der[0], dk1 = der[1], cwk = cw[0], chk = ch[0];
#pragma unroll
    for (int i = 1; i < 8; ++i) {
        bool sel = (idx == i);
        wk  = sel ? w[i]      : wk;
        hk  = sel ? h[i]      : hk;
        dk  = sel ? der[i]    : dk;
        dk1 = sel ? der[i + 1]: dk1;
        cwk = sel ? cw[i]     : cwk;
        chk = sel ? ch[i]     : chk;
    }

    float xi = (xc - cwk) / wk;
    xi = fminf(fmaxf(xi, 1e-6f), 1.f - 1e-6f);
    float om = 1.f - xi;
    float s  = hk / wk;
    float num = hk * (s * xi * xi + dk * xi * om);
    float den = s + (dk + dk1 - 2.f * s) * xi * om;
    float yin = chk + num / den;
    float nld = s * s * (dk1 * xi * xi + 2.f * s * xi * om + dk * om * om);
    float ldin = logf(nld + 1e-8f) - logf(den * den + 1e-8f);

    y_out  = inside ? yin  : xv;
    ld_out = inside ? ldin : 0.f;
}

// ---------------------------------------------------------------------------
// Fused kernel
// ---------------------------------------------------------------------------
__global__ void __launch_bounds__(THREADS, 1)
spline_fused(const float* __restrict__ x,
             const float* __restrict__ W1, const float* __restrict__ b1,
             const float* __restrict__ W2, const float* __restrict__ b2,
             const float* __restrict__ W3, const float* __restrict__ b3,
             float* __restrict__ out)
{
    extern __shared__ float sm[];
    const int tid  = threadIdx.x;
    const int row0 = blockIdx.x * TM;

    // Load x tile (transposed into smem); copy masked half straight to output.
    for (int idx = tid; idx < TM * DIM; idx += THREADS) {
        int r = idx >> 6, c = idx & 63;
        float v = x[(row0 + r) * DIM + c];
        if (c < D_IN) {
            sm[OFF_XM + c * HSTR + r] = v;
            out[(row0 + r) * DIM + c] = v;
        } else {
            sm[OFF_XT + (c - D_IN) * HSTR + r] = v;
        }
    }
    __syncthreads();

    mlp_layer<D_IN>(sm + OFF_XM, W1, b1, sm + OFF_H1, tid);
    __syncthreads();
    mlp_layer<HIDDEN>(sm + OFF_H1, W2, b2, sm + OFF_H2, tid);
    __syncthreads();

    // ---- stage 3: raw = h2 @ W3 + b3, per-thread 23 cols (one spline group)
    //      x 4 rows, rows packed in f32x2 pairs; W3 staged in smem per k-chunk
    const int d   = tid & 31;     // spline dim 0..31
    const int rg3 = tid >> 5;     // 0..7 -> rows rg3*4 .. +3

    ull acc[23][2];
#pragma unroll
    for (int j = 0; j < 23; ++j) {
        float bv = b3[d * 23 + j];
        ull bb = pk(bv, bv);
        acc[j][0] = bb; acc[j][1] = bb;
    }

    for (int k0 = 0; k0 < HIDDEN; k0 += KC3) {
        // cooperative stage of W3[k0:k0+16][0:736] into smem (coalesced float4)
        for (int idx = tid; idx < KC3 * (OUTD / 4); idx += THREADS) {
            int rr = idx / (OUTD / 4), cc = idx % (OUTD / 4);
            float4 v = *reinterpret_cast<const float4*>(W3 + (k0 + rr) * OUTD + cc * 4);
            *reinterpret_cast<float4*>(sm + OFF_W3 + rr * OUTD + cc * 4) = v;
        }
        __syncthreads();

#pragma unroll 2
        for (int kk = 0; kk < KC3; ++kk) {
            ull a0 = *reinterpret_cast<const ull*>(sm + OFF_H2 + (k0 + kk) * HSTR + rg3 * 4);
            ull a1 = *reinterpret_cast<const ull*>(sm + OFF_H2 + (k0 + kk) * HSTR + rg3 * 4 + 2);
            const float* wrow = sm + OFF_W3 + kk * OUTD + d * 23;
#pragma unroll
            for (int j = 0; j < 23; ++j) {
                float bv = wrow[j];        // conflict-free: 23*d distinct mod 32
                ull bb = pk(bv, bv);
                fma2(acc[j][0], a0, bb);
                fma2(acc[j][1], a1, bb);
            }
        }
        __syncthreads();
    }

    // ---- spline + output
    float xt_v[4];
#pragma unroll
    for (int i = 0; i < 4; ++i)
        xt_v[i] = sm[OFF_XT + d * HSTR + rg3 * 4 + i];

#pragma unroll
    for (int i = 0; i < 4; ++i) {
        float raw[23];
#pragma unroll
        for (int j = 0; j < 23; ++j) {
            float lo, hi; unpk(acc[j][i >> 1], lo, hi);
            raw[j] = (i & 1) ? hi : lo;
        }
        float yv, ld;
        spline_eval(raw, xt_v[i], yv, ld);

        int gr = row0 + rg3 * 4 + i;
        out[gr * DIM + D_IN + d] = yv;          // coalesced: 32 lanes = 32 cols

        // deterministic warp-tree reduction of log_det over the 32 dims
#pragma unroll
        for (int off = 16; off; off >>= 1)
            ld += __shfl_xor_sync(0xffffffffu, ld, off);
        if (d == 0) out[B_ROWS * DIM + gr] = ld;
    }
}

// ---------------------------------------------------------------------------
extern "C" void kernel_launch(void* const* d_in, const int* in_sizes, int n_in,
                              void* d_out, int out_size)
{
    (void)in_sizes; (void)n_in; (void)out_size;
    const float* x  = (const float*)d_in[0];
    const float* W1 = (const float*)d_in[1];
    const float* b1 = (const float*)d_in[2];
    const float* W2 = (const float*)d_in[3];
    const float* b2 = (const float*)d_in[4];
    const float* W3 = (const float*)d_in[5];
    const float* b3 = (const float*)d_in[6];
    float* out = (float*)d_out;

    size_t smem = SMEM_FLOATS * sizeof(float);  // 195072 B
    cudaFuncSetAttribute(spline_fused,
                         cudaFuncAttributeMaxDynamicSharedMemorySize, (int)smem);
    spline_fused<<<B_ROWS / TM, THREADS, smem>>>(x, W1, b1, W2, b2, W3, b3, out);
}

// round 2
// speedup vs baseline: 1.0018x; 1.0018x over previous
#include <cuda_runtime.h>
#include <cstdint>

// ---------------------------------------------------------------------------
// SplineCouplingLayer fused kernel (round 1: fp32 + packed f32x2 FMA)
//
//  x[B,64] -> split 32/32
//  h1 = relu(xm @ W1 + b1)        [B,512]
//  h2 = relu(h1 @ W2 + b2)        [B,512]
//  raw = h2 @ W3 + b3             [B,736] = [B,32,23]
//  (y_t, ld) = rq_spline(x_t, raw)
//  out = [ y[B,64] , sum_ld[B] ]   (flattened tuple order)
// ---------------------------------------------------------------------------

#define B_ROWS  131072
#define DIM     64
#define D_IN    32
#define D_OUT   32
#define HIDDEN  512
#define OUTD    736          // 32 * 23
#define TAILB   3.0f

#define TM      32           // rows per block
#define THREADS 256
#define HSTR    34           // padded stride (even -> 8B-aligned row pairs)
#define KC3     16           // k-chunk for stage 3 W3 staging

// smem layout (float offsets)
#define OFF_H1  0
#define OFF_H2  (OFF_H1 + HIDDEN * HSTR)             // 17408
#define OFF_W3  (OFF_H2 + HIDDEN * HSTR)             // 34816
#define OFF_XM  (OFF_W3 + KC3 * OUTD)                // 46592
#define OFF_XT  (OFF_XM + D_IN * HSTR)               // 47680
#define SMEM_FLOATS (OFF_XT + D_OUT * HSTR)          // 48768 -> 195072 bytes

typedef unsigned long long ull;

__device__ __forceinline__ ull pk(float lo, float hi) {
    ull r; asm("mov.b64 %0, {%1, %2};" : "=l"(r) : "f"(lo), "f"(hi)); return r;
}
__device__ __forceinline__ void unpk(ull v, float &lo, float &hi) {
    asm("mov.b64 {%0, %1}, %2;" : "=f"(lo), "=f"(hi) : "l"(v));
}
// packed 2-wide fp32 FMA (Blackwell sm_100+): d = a*b + d elementwise on halves
__device__ __forceinline__ void fma2(ull &d, ull a, ull b) {
    asm("fma.rn.f32x2 %0, %1, %2, %0;" : "+l"(d) : "l"(a), "l"(b));
}

// ---------------------------------------------------------------------------
// One MLP layer: out[32, 512] = relu(aT^T @ W + bias), a/out stored transposed
// in smem as [col][row] with stride HSTR. Per-thread 8 rows x 8 cols, rows
// packed in f32x2 pairs. W read from global (L1/L2 resident).
// ---------------------------------------------------------------------------
template<int K>
__device__ __forceinline__ void mlp_layer(const float* __restrict__ aT,
                                          const float* __restrict__ W,
                                          const float* __restrict__ bias,
                                          float* __restrict__ outT, int tid)
{
    const int cg = tid & 63;      // 64 col groups
    const int rg = tid >> 6;      // 4  row groups
    const int c0 = cg * 8;
    const int r0 = rg * 8;

    ull acc[8][4];                // [col][rowpair]
#pragma unroll
    for (int j = 0; j < 8; ++j) {
        float bv = bias[c0 + j];
        ull bb = pk(bv, bv);
#pragma unroll
        for (int p = 0; p < 4; ++p) acc[j][p] = bb;
    }

#pragma unroll 4
    for (int k = 0; k < K; ++k) {
        ull a2[4];
#pragma unroll
        for (int p = 0; p < 4; ++p)
            a2[p] = *reinterpret_cast<const ull*>(aT + k * HSTR + r0 + 2 * p);
        float4 bA = *reinterpret_cast<const float4*>(W + k * HIDDEN + c0);
        float4 bB = *reinterpret_cast<const float4*>(W + k * HIDDEN + c0 + 4);
        ull bb[8];
        bb[0] = pk(bA.x, bA.x); bb[1] = pk(bA.y, bA.y);
        bb[2] = pk(bA.z, bA.z); bb[3] = pk(bA.w, bA.w);
        bb[4] = pk(bB.x, bB.x); bb[5] = pk(bB.y, bB.y);
        bb[6] = pk(bB.z, bB.z); bb[7] = pk(bB.w, bB.w);
#pragma unroll
        for (int j = 0; j < 8; ++j)
#pragma unroll
            for (int p = 0; p < 4; ++p)
                fma2(acc[j][p], a2[p], bb[j]);
    }

#pragma unroll
    for (int j = 0; j < 8; ++j)
#pragma unroll
        for (int p = 0; p < 4; ++p) {
            float lo, hi; unpk(acc[j][p], lo, hi);
            lo = fmaxf(lo, 0.f); hi = fmaxf(hi, 0.f);
            float* o = outT + (c0 + j) * HSTR + r0 + 2 * p;
            o[0] = lo; o[1] = hi;
        }
}

// ---------------------------------------------------------------------------
// Rational-quadratic spline (register-resident, SEL-chain gathers)
// ---------------------------------------------------------------------------
__device__ __forceinline__ float softplusf(float z) {
    return (z > 20.f) ? z : log1pf(expf(z));
}

__device__ __forceinline__ void spline_eval(const float raw[23], float xv,
                                            float &y_out, float &ld_out)
{
    float w[8], h[8];
    float mw = raw[0], mh = raw[8];
#pragma unroll
    for (int i = 1; i < 8; ++i) { mw = fmaxf(mw, raw[i]); mh = fmaxf(mh, raw[8 + i]); }
    float sw = 0.f, sh = 0.f;
#pragma unroll
    for (int i = 0; i < 8; ++i) {
        w[i] = expf(raw[i] - mw);     sw += w[i];
        h[i] = expf(raw[8 + i] - mh); sh += h[i];
    }
    float iw = 6.f / sw, ih = 6.f / sh;   // softmax * 2*tail_bound
#pragma unroll
    for (int i = 0; i < 8; ++i) { w[i] *= iw; h[i] *= ih; }

    float der[9];
    der[0] = 1.f; der[8] = 1.f;
#pragma unroll
    for (int i = 0; i < 7; ++i) der[i + 1] = softplusf(raw[16 + i]);

    float cw[9], ch[9];
    cw[0] = -TAILB; ch[0] = -TAILB;
#pragma unroll
    for (int i = 0; i < 8; ++i) { cw[i + 1] = cw[i] + w[i]; ch[i + 1] = ch[i] + h[i]; }

    bool inside = (xv >= -TAILB) && (xv <= TAILB);
    float xc = fminf(fmaxf(xv, -TAILB + 1e-6f), TAILB - 1e-6f);

    int idx = 0;
#pragma unroll
    for (int i = 1; i <= 8; ++i) idx += (cw[i] < xc) ? 1 : 0;
    idx = min(idx, 7);

    float wk = w[0], hk = h[0], dk = der[0], dk1 = der[1], cwk = cw[0], chk = ch[0];
#pragma unroll
    for (int i = 1; i < 8; ++i) {
        bool sel = (idx == i);
        wk  = sel ? w[i]      : wk;
        hk  = sel ? h[i]      : hk;
        dk  = sel ? der[i]    : dk;
        dk1 = sel ? der[i + 1]: dk1;
        cwk = sel ? cw[i]     : cwk;
        chk = sel ? ch[i]     : chk;
    }

    float xi = (xc - cwk) / wk;
    xi = fminf(fmaxf(xi, 1e-6f), 1.f - 1e-6f);
    float om = 1.f - xi;
    float s  = hk / wk;
    float num = hk * (s * xi * xi + dk * xi * om);
    float den = s + (dk + dk1 - 2.f * s) * xi * om;
    float yin = chk + num / den;
    float nld = s * s * (dk1 * xi * xi + 2.f * s * xi * om + dk * om * om);
    float ldin = logf(nld + 1e-8f) - logf(den * den + 1e-8f);

    y_out  = inside ? yin  : xv;
    ld_out = inside ? ldin : 0.f;
}

// ---------------------------------------------------------------------------
// Fused kernel
// ---------------------------------------------------------------------------
__global__ void __launch_bounds__(THREADS, 1)
spline_fused(const float* __restrict__ x,
             const float* __restrict__ W1, const float* __restrict__ b1,
             const float* __restrict__ W2, const float* __restrict__ b2,
             const float* __restrict__ W3, const float* __restrict__ b3,
             float* __restrict__ out)
{
    extern __shared__ float sm[];
    const int tid  = threadIdx.x;
    const int row0 = blockIdx.x * TM;

    // Load x tile (transposed into smem); copy masked half straight to output.
    for (int idx = tid; idx < TM * DIM; idx += THREADS) {
        int r = idx >> 6, c = idx & 63;
        float v = x[(row0 + r) * DIM + c];
        if (c < D_IN) {
            sm[OFF_XM + c * HSTR + r] = v;
            out[(row0 + r) * DIM + c] = v;
        } else {
            sm[OFF_XT + (c - D_IN) * HSTR + r] = v;
        }
    }
    __syncthreads();

    mlp_layer<D_IN>(sm + OFF_XM, W1, b1, sm + OFF_H1, tid);
    __syncthreads();
    mlp_layer<HIDDEN>(sm + OFF_H1, W2, b2, sm + OFF_H2, tid);
    __syncthreads();

    // ---- stage 3: raw = h2 @ W3 + b3, per-thread 23 cols (one spline group)
    //      x 4 rows, rows packed in f32x2 pairs; W3 staged in smem per k-chunk
    const int d   = tid & 31;     // spline dim 0..31
    const int rg3 = tid >> 5;     // 0..7 -> rows rg3*4 .. +3

    ull acc[23][2];
#pragma unroll
    for (int j = 0; j < 23; ++j) {
        float bv = b3[d * 23 + j];
        ull bb = pk(bv, bv);
        acc[j][0] = bb; acc[j][1] = bb;
    }

    for (int k0 = 0; k0 < HIDDEN; k0 += KC3) {
        // cooperative stage of W3[k0:k0+16][0:736] into smem (coalesced float4)
        for (int idx = tid; idx < KC3 * (OUTD / 4); idx += THREADS) {
            int rr = idx / (OUTD / 4), cc = idx % (OUTD / 4);
            float4 v = *reinterpret_cast<const float4*>(W3 + (k0 + rr) * OUTD + cc * 4);
            *reinterpret_cast<float4*>(sm + OFF_W3 + rr * OUTD + cc * 4) = v;
        }
        __syncthreads();

#pragma unroll 2
        for (int kk = 0; kk < KC3; ++kk) {
            ull a0 = *reinterpret_cast<const ull*>(sm + OFF_H2 + (k0 + kk) * HSTR + rg3 * 4);
            ull a1 = *reinterpret_cast<const ull*>(sm + OFF_H2 + (k0 + kk) * HSTR + rg3 * 4 + 2);
            const float* wrow = sm + OFF_W3 + kk * OUTD + d * 23;
#pragma unroll
            for (int j = 0; j < 23; ++j) {
                float bv = wrow[j];        // conflict-free: 23*d distinct mod 32
                ull bb = pk(bv, bv);
                fma2(acc[j][0], a0, bb);
                fma2(acc[j][1], a1, bb);
            }
        }
        __syncthreads();
    }

    // ---- spline + output
    float xt_v[4];
#pragma unroll
    for (int i = 0; i < 4; ++i)
        xt_v[i] = sm[OFF_XT + d * HSTR + rg3 * 4 + i];

#pragma unroll
    for (int i = 0; i < 4; ++i) {
        float raw[23];
#pragma unroll
        for (int j = 0; j < 23; ++j) {
            float lo, hi; unpk(acc[j][i >> 1], lo, hi);
            raw[j] = (i & 1) ? hi : lo;
        }
        float yv, ld;
        spline_eval(raw, xt_v[i], yv, ld);

        int gr = row0 + rg3 * 4 + i;
        out[gr * DIM + D_IN + d] = yv;          // coalesced: 32 lanes = 32 cols

        // deterministic warp-tree reduction of log_det over the 32 dims
#pragma unroll
        for (int off = 16; off; off >>= 1)
            ld += __shfl_xor_sync(0xffffffffu, ld, off);
        if (d == 0) out[B_ROWS * DIM + gr] = ld;
    }
}

// ---------------------------------------------------------------------------
extern "C" void kernel_launch(void* const* d_in, const int* in_sizes, int n_in,
                              void* d_out, int out_size)
{
    (void)in_sizes; (void)n_in; (void)out_size;
    const float* x  = (const float*)d_in[0];
    const float* W1 = (const float*)d_in[1];
    const float* b1 = (const float*)d_in[2];
    const float* W2 = (const float*)d_in[3];
    const float* b2 = (const float*)d_in[4];
    const float* W3 = (const float*)d_in[5];
    const float* b3 = (const float*)d_in[6];
    float* out = (float*)d_out;

    size_t smem = SMEM_FLOATS * sizeof(float);  // 195072 B
    cudaFuncSetAttribute(spline_fused,
                         cudaFuncAttributeMaxDynamicSharedMemorySize, (int)smem);
    spline_fused<<<B_ROWS / TM, THREADS, smem>>>(x, W1, b1, W2, b2, W3, b3, out);
}

// round 4
// speedup vs baseline: 1.0396x; 1.0377x over previous
#include <cuda_runtime.h>
#include <cstdint>

// ---------------------------------------------------------------------------
// SplineCouplingLayer fused kernel (round 3: round-2 design, compile fix)
//  - smem-staged W2/W3, double-buffered k-chunks
//  - strided column ownership (conflict-free LDS.32 for B operand)
//  - packed f32x2 FMA throughout
// ---------------------------------------------------------------------------

#define B_ROWS  131072
#define DIM     64
#define D_IN    32
#define D_OUT   32
#define HIDDEN  512
#define OUTD    736          // 32 * 23
#define TAILB   3.0f

#define TM      32           // rows per block
#define THREADS 256
#define HSTR    34           // padded stride for transposed activations
#define KC      16           // k-chunk for W2/W3 staging

// smem layout (float offsets)
#define OFF_H2   0                                   // 512*34 = 17408
#define OFF_A    17408                               // overlay region
#define OFF_H1   OFF_A                               // phase 2: 17408 fl
#define OFF_W2   (OFF_A + 17408)                     // phase 2: 2*16*512 = 16384 fl
#define OFF_W3   OFF_A                               // phase 3: 2*16*736 = 23552 fl
#define OFF_XT   51200                               // 32*34 = 1088
#define OFF_XM   52288                               // 32*34 = 1088
#define SMEM_FLOATS 53376                            // 213504 bytes

#define W2_CHUNK_F4 2048                             // 16*512/4
#define W3_CHUNK_F4 2944                             // 16*736/4

typedef unsigned long long ull;

__device__ __forceinline__ ull pk(float lo, float hi) {
    ull r; asm("mov.b64 %0, {%1, %2};" : "=l"(r) : "f"(lo), "f"(hi)); return r;
}
__device__ __forceinline__ void unpk(ull v, float &lo, float &hi) {
    asm("mov.b64 {%0, %1}, %2;" : "=f"(lo), "=f"(hi) : "l"(v));
}
// packed 2-wide fp32 FMA (Blackwell): d = a*b + d elementwise on halves
__device__ __forceinline__ void fma2(ull &d, ull a, ull b) {
    asm("fma.rn.f32x2 %0, %1, %2, %0;" : "+l"(d) : "l"(a), "l"(b));
}

// ---------------------------------------------------------------------------
// Spline (register-resident)
// ---------------------------------------------------------------------------
__device__ __forceinline__ float softplusf(float z) {
    return (z > 20.f) ? z : log1pf(expf(z));
}

__device__ __forceinline__ void spline_eval(const float raw[23], float xv,
                                            float &y_out, float &ld_out)
{
    float w[8], h[8];
    float mw = raw[0], mh = raw[8];
#pragma unroll
    for (int i = 1; i < 8; ++i) { mw = fmaxf(mw, raw[i]); mh = fmaxf(mh, raw[8 + i]); }
    float sw = 0.f, sh = 0.f;
#pragma unroll
    for (int i = 0; i < 8; ++i) {
        w[i] = expf(raw[i] - mw);     sw += w[i];
        h[i] = expf(raw[8 + i] - mh); sh += h[i];
    }
    float iw = 6.f / sw, ih = 6.f / sh;
#pragma unroll
    for (int i = 0; i < 8; ++i) { w[i] *= iw; h[i] *= ih; }

    float der[9];
    der[0] = 1.f; der[8] = 1.f;
#pragma unroll
    for (int i = 0; i < 7; ++i) der[i + 1] = softplusf(raw[16 + i]);

    float cw[9], ch[9];
    cw[0] = -TAILB; ch[0] = -TAILB;
#pragma unroll
    for (int i = 0; i < 8; ++i) { cw[i + 1] = cw[i] + w[i]; ch[i + 1] = ch[i] + h[i]; }

    bool inside = (xv >= -TAILB) && (xv <= TAILB);
    float xc = fminf(fmaxf(xv, -TAILB + 1e-6f), TAILB - 1e-6f);

    int idx = 0;
#pragma unroll
    for (int i = 1; i <= 8; ++i) idx += (cw[i] < xc) ? 1 : 0;
    idx = min(idx, 7);

    float wk = w[0], hk = h[0], dk = der[0], dk1 = der[1], cwk = cw[0], chk = ch[0];
#pragma unroll
    for (int i = 1; i < 8; ++i) {
        bool sel = (idx == i);
        wk  = sel ? w[i]      : wk;
        hk  = sel ? h[i]      : hk;
        dk  = sel ? der[i]    : dk;
        dk1 = sel ? der[i + 1]: dk1;
        cwk = sel ? cw[i]     : cwk;
        chk = sel ? ch[i]     : chk;
    }

    float xi = (xc - cwk) / wk;
    xi = fminf(fmaxf(xi, 1e-6f), 1.f - 1e-6f);
    float om = 1.f - xi;
    float s  = hk / wk;
    float num = hk * (s * xi * xi + dk * xi * om);
    float den = s + (dk + dk1 - 2.f * s) * xi * om;
    float yin = chk + num / den;
    float nld = s * s * (dk1 * xi * xi + 2.f * s * xi * om + dk * om * om);
    float ldin = logf(nld + 1e-8f) - logf(den * den + 1e-8f);

    y_out  = inside ? yin  : xv;
    ld_out = inside ? ldin : 0.f;
}

// ---------------------------------------------------------------------------
// Fused kernel
// ---------------------------------------------------------------------------
__global__ void __launch_bounds__(THREADS, 1)
spline_fused(const float* __restrict__ x,
             const float* __restrict__ W1, const float* __restrict__ b1,
             const float* __restrict__ W2, const float* __restrict__ b2,
             const float* __restrict__ W3, const float* __restrict__ b3,
             float* __restrict__ out)
{
    extern __shared__ float sm[];
    const int tid  = threadIdx.x;
    const int row0 = blockIdx.x * TM;

    // thread mapping for layers 1/2 (strided columns: c = cg + 64*j)
    const int cg = tid & 63;
    const int rg = tid >> 6;
    const int r0 = rg * 8;

    // ---- load x tile (transposed); copy masked half straight to output
    for (int idx = tid; idx < TM * DIM; idx += THREADS) {
        int r = idx >> 6, c = idx & 63;
        float v = x[(row0 + r) * DIM + c];
        if (c < D_IN) {
            sm[OFF_XM + c * HSTR + r] = v;
            out[(row0 + r) * DIM + c] = v;
        } else {
            sm[OFF_XT + (c - D_IN) * HSTR + r] = v;
        }
    }
    __syncthreads();

    // =====================================================================
    // Layer 1: h1 = relu(xm @ W1 + b1), K=32, W1 direct from global (small)
    // =====================================================================
    {
        ull acc[8][4];
#pragma unroll
        for (int j = 0; j < 8; ++j) {
            float bv = b1[cg + 64 * j];
            ull bb = pk(bv, bv);
#pragma unroll
            for (int p = 0; p < 4; ++p) acc[j][p] = bb;
        }
#pragma unroll 4
        for (int k = 0; k < D_IN; ++k) {
            ull a2[4];
#pragma unroll
            for (int p = 0; p < 4; ++p)
                a2[p] = *reinterpret_cast<const ull*>(sm + OFF_XM + k * HSTR + r0 + 2 * p);
#pragma unroll
            for (int j = 0; j < 8; ++j) {
                float bv = __ldg(W1 + k * HIDDEN + cg + 64 * j);
                ull bb = pk(bv, bv);
#pragma unroll
                for (int p = 0; p < 4; ++p) fma2(acc[j][p], a2[p], bb);
            }
        }
#pragma unroll
        for (int j = 0; j < 8; ++j)
#pragma unroll
            for (int p = 0; p < 4; ++p) {
                float lo, hi; unpk(acc[j][p], lo, hi);
                *reinterpret_cast<float2*>(sm + OFF_H1 + (cg + 64 * j) * HSTR + r0 + 2 * p)
                    = make_float2(fmaxf(lo, 0.f), fmaxf(hi, 0.f));
            }
    }
    __syncthreads();

    // =====================================================================
    // Layer 2: h2 = relu(h1 @ W2 + b2), K=512, W2 staged in smem (dbl buf)
    // =====================================================================
    {
        ull acc[8][4];
#pragma unroll
        for (int j = 0; j < 8; ++j) {
            float bv = b2[cg + 64 * j];
            ull bb = pk(bv, bv);
#pragma unroll
            for (int p = 0; p < 4; ++p) acc[j][p] = bb;
        }

        // prologue: stage chunk 0
        {
            const float4* src = reinterpret_cast<const float4*>(W2);
            float4* dst = reinterpret_cast<float4*>(sm + OFF_W2);
#pragma unroll
            for (int t = 0; t < 8; ++t) {
                float4 v = __ldg(src + tid + 256 * t);
                dst[tid + 256 * t] = v;
            }
        }
        __syncthreads();

        for (int c = 0; c < HIDDEN / KC; ++c) {
            float4 st[8];
            const bool more = (c + 1 < HIDDEN / KC);
            if (more) {
                const float4* src = reinterpret_cast<const float4*>(W2) + (c + 1) * W2_CHUNK_F4;
#pragma unroll
                for (int t = 0; t < 8; ++t) st[t] = __ldg(src + tid + 256 * t);
            }

            const float* wbuf = sm + OFF_W2 + (c & 1) * (KC * HIDDEN);
            const float* abuf = sm + OFF_H1 + (c * KC) * HSTR;
#pragma unroll 4
            for (int kk = 0; kk < KC; ++kk) {
                ull a2[4];
#pragma unroll
                for (int p = 0; p < 4; ++p)
                    a2[p] = *reinterpret_cast<const ull*>(abuf + kk * HSTR + r0 + 2 * p);
#pragma unroll
                for (int j = 0; j < 8; ++j) {
                    float bv = wbuf[kk * HIDDEN + cg + 64 * j];
                    ull bb = pk(bv, bv);
#pragma unroll
                    for (int p = 0; p < 4; ++p) fma2(acc[j][p], a2[p], bb);
                }
            }

            if (more) {
                float4* dst = reinterpret_cast<float4*>(sm + OFF_W2) + ((c + 1) & 1) * W2_CHUNK_F4;
#pragma unroll
                for (int t = 0; t < 8; ++t) dst[tid + 256 * t] = st[t];
            }
            __syncthreads();
        }

#pragma unroll
        for (int j = 0; j < 8; ++j)
#pragma unroll
            for (int p = 0; p < 4; ++p) {
                float lo, hi; unpk(acc[j][p], lo, hi);
                *reinterpret_cast<float2*>(sm + OFF_H2 + (cg + 64 * j) * HSTR + r0 + 2 * p)
                    = make_float2(fmaxf(lo, 0.f), fmaxf(hi, 0.f));
            }
    }
    __syncthreads();

    // =====================================================================
    // Layer 3: raw = h2 @ W3 + b3, 23 cols x 4 rows per thread, W3 staged
    // =====================================================================
    const int d   = tid & 31;     // spline dim 0..31
    const int rg3 = tid >> 5;     // row group 0..7 (4 rows each)

    ull acc[23][2];
#pragma unroll
    for (int j = 0; j < 23; ++j) {
        float bv = b3[d * 23 + j];
        ull bb = pk(bv, bv);
        acc[j][0] = bb; acc[j][1] = bb;
    }

    // prologue: stage W3 chunk 0
    {
        const float4* src = reinterpret_cast<const float4*>(W3);
        float4* dst = reinterpret_cast<float4*>(sm + OFF_W3);
#pragma unroll
        for (int t = 0; t < 12; ++t) {
            int idx = tid + 256 * t;
            if (idx < W3_CHUNK_F4) dst[idx] = __ldg(src + idx);
        }
    }
    __syncthreads();

    for (int c = 0; c < HIDDEN / KC; ++c) {
        float4 st[12];
        const bool more = (c + 1 < HIDDEN / KC);
        if (more) {
            const float4* src = reinterpret_cast<const float4*>(W3) + (c + 1) * W3_CHUNK_F4;
#pragma unroll
            for (int t = 0; t < 12; ++t) {
                int idx = tid + 256 * t;
                if (idx < W3_CHUNK_F4) st[t] = __ldg(src + idx);
            }
        }

        const float* wbuf = sm + OFF_W3 + (c & 1) * (KC * OUTD);
        const float* abuf = sm + OFF_H2 + (c * KC) * HSTR;
#pragma unroll 2
        for (int kk = 0; kk < KC; ++kk) {
            ull a0 = *reinterpret_cast<const ull*>(abuf + kk * HSTR + rg3 * 4);
            ull a1 = *reinterpret_cast<const ull*>(abuf + kk * HSTR + rg3 * 4 + 2);
            const float* wrow = wbuf + kk * OUTD + d * 23;
#pragma unroll
            for (int j = 0; j < 23; ++j) {
                float bv = wrow[j];        // conflict-free: 23*d distinct mod 32
                ull bb = pk(bv, bv);
                fma2(acc[j][0], a0, bb);
                fma2(acc[j][1], a1, bb);
            }
        }

        if (more) {
            float4* dst = reinterpret_cast<float4*>(sm + OFF_W3) + ((c + 1) & 1) * W3_CHUNK_F4;
#pragma unroll
            for (int t = 0; t < 12; ++t) {
                int idx = tid + 256 * t;
                if (idx < W3_CHUNK_F4) dst[idx] = st[t];
            }
        }
        __syncthreads();
    }

    // ---- spline + output
    float xt_v[4];
#pragma unroll
    for (int i = 0; i < 4; ++i)
        xt_v[i] = sm[OFF_XT + d * HSTR + rg3 * 4 + i];

#pragma unroll
    for (int i = 0; i < 4; ++i) {
        float raw[23];
#pragma unroll
        for (int j = 0; j < 23; ++j) {
            float lo, hi; unpk(acc[j][i >> 1], lo, hi);
            raw[j] = (i & 1) ? hi : lo;
        }
        float yv, ld;
        spline_eval(raw, xt_v[i], yv, ld);

        int gr = row0 + rg3 * 4 + i;
        out[gr * DIM + D_IN + d] = yv;

#pragma unroll
        for (int off = 16; off; off >>= 1)
            ld += __shfl_xor_sync(0xffffffffu, ld, off);
        if (d == 0) out[B_ROWS * DIM + gr] = ld;
    }
}

// ---------------------------------------------------------------------------
extern "C" void kernel_launch(void* const* d_in, const int* in_sizes, int n_in,
                              void* d_out, int out_size)
{
    (void)in_sizes; (void)n_in; (void)out_size;
    const float* x  = (const float*)d_in[0];
    const float* W1 = (const float*)d_in[1];
    const float* b1 = (const float*)d_in[2];
    const float* W2 = (const float*)d_in[3];
    const float* b2 = (const float*)d_in[4];
    const float* W3 = (const float*)d_in[5];
    const float* b3 = (const float*)d_in[6];
    float* out = (float*)d_out;

    size_t smem = SMEM_FLOATS * sizeof(float);  // 213504 B
    cudaFuncSetAttribute(spline_fused,
                         cudaFuncAttributeMaxDynamicSharedMemorySize, (int)smem);
    spline_fused<<<B_ROWS / TM, THREADS, smem>>>(x, W1, b1, W2, b2, W3, b3, out);
}